// round 2
// baseline (speedup 1.0000x reference)
#include <cuda_runtime.h>

#define NJ 24

__global__ void skin_kernel(const float* __restrict__ normals,
                            const float* __restrict__ pose,
                            const float* __restrict__ W,
                            float* __restrict__ out,
                            int N)
{
    __shared__ float sLoc[NJ][9];  // local (per-joint) rotations
    __shared__ float sR[NJ][9];    // composed global rotations

    const int b = blockIdx.y;
    const int tid = threadIdx.x;

    // --- Rodrigues for 24 joints (one thread per joint) ---
    if (tid < NJ) {
        const float x = pose[b * 72 + tid * 3 + 0];
        const float y = pose[b * 72 + tid * 3 + 1];
        const float z = pose[b * 72 + tid * 3 + 2];
        const float e = 1e-8f;
        // reference: angle = ||axisang + eps||, axis = axisang / angle
        const float a = sqrtf((x + e) * (x + e) + (y + e) * (y + e) + (z + e) * (z + e));
        const float inv = 1.0f / a;
        const float ux = x * inv, uy = y * inv, uz = z * inv;
        float s, c;
        sincosf(a, &s, &c);
        const float C = 1.0f - c;
        sLoc[tid][0] = c + C * ux * ux;
        sLoc[tid][1] = C * ux * uy - s * uz;
        sLoc[tid][2] = C * ux * uz + s * uy;
        sLoc[tid][3] = C * uy * ux + s * uz;
        sLoc[tid][4] = c + C * uy * uy;
        sLoc[tid][5] = C * uy * uz - s * ux;
        sLoc[tid][6] = C * uz * ux - s * uy;
        sLoc[tid][7] = C * uz * uy + s * ux;
        sLoc[tid][8] = c + C * uz * uz;
    }
    __syncthreads();

    // --- kinematic chain composition (serial, thread 0; parents always < child) ---
    if (tid == 0) {
        const int par[NJ] = {-1, 0, 0, 0, 1, 2, 3, 4, 5, 6, 7, 8, 9, 9, 9, 12, 13, 14, 16, 17, 18, 19, 20, 21};
        #pragma unroll
        for (int i = 0; i < 9; i++) sR[0][i] = sLoc[0][i];
        for (int j = 1; j < NJ; j++) {
            const float* P = sR[par[j]];
            const float* L = sLoc[j];
            float Rm[9];
            #pragma unroll
            for (int r = 0; r < 3; r++)
                #pragma unroll
                for (int cc = 0; cc < 3; cc++)
                    Rm[r * 3 + cc] = P[r * 3 + 0] * L[0 * 3 + cc]
                                   + P[r * 3 + 1] * L[1 * 3 + cc]
                                   + P[r * 3 + 2] * L[2 * 3 + cc];
            #pragma unroll
            for (int i = 0; i < 9; i++) sR[j][i] = Rm[i];
        }
    }
    __syncthreads();

    // --- per-point skinning: 4 points per thread via float4 ---
    const int g = blockIdx.x * blockDim.x + tid;
    const int n = g * 4;
    if (n >= N) return;

    float4 acc[9];
    #pragma unroll
    for (int i = 0; i < 9; i++) acc[i] = make_float4(0.f, 0.f, 0.f, 0.f);

    const float* Wb = W + (size_t)b * NJ * N;
    #pragma unroll
    for (int k = 0; k < NJ; k++) {
        const float4 w = *reinterpret_cast<const float4*>(Wb + (size_t)k * N + n);
        #pragma unroll
        for (int e2 = 0; e2 < 9; e2++) {
            const float r = sR[k][e2];
            acc[e2].x = fmaf(r, w.x, acc[e2].x);
            acc[e2].y = fmaf(r, w.y, acc[e2].y);
            acc[e2].z = fmaf(r, w.z, acc[e2].z);
            acc[e2].w = fmaf(r, w.w, acc[e2].w);
        }
    }

    const float* Nb = normals + (size_t)b * 3 * N;
    const float4 nx = *reinterpret_cast<const float4*>(Nb + 0 * (size_t)N + n);
    const float4 ny = *reinterpret_cast<const float4*>(Nb + 1 * (size_t)N + n);
    const float4 nz = *reinterpret_cast<const float4*>(Nb + 2 * (size_t)N + n);

    float* Ob = out + (size_t)b * 3 * N;
    #pragma unroll
    for (int i = 0; i < 3; i++) {
        float4 o;
        o.x = acc[i * 3 + 0].x * nx.x + acc[i * 3 + 1].x * ny.x + acc[i * 3 + 2].x * nz.x;
        o.y = acc[i * 3 + 0].y * nx.y + acc[i * 3 + 1].y * ny.y + acc[i * 3 + 2].y * nz.y;
        o.z = acc[i * 3 + 0].z * nx.z + acc[i * 3 + 1].z * ny.z + acc[i * 3 + 2].z * nz.z;
        o.w = acc[i * 3 + 0].w * nx.w + acc[i * 3 + 1].w * ny.w + acc[i * 3 + 2].w * nz.w;
        *reinterpret_cast<float4*>(Ob + (size_t)i * N + n) = o;
    }
}

extern "C" void kernel_launch(void* const* d_in, const int* in_sizes, int n_in,
                              void* d_out, int out_size)
{
    const float* normals = (const float*)d_in[0];   // (B,3,N)
    const float* pose    = (const float*)d_in[1];   // (B,72)
    const float* weights = (const float*)d_in[2];   // (B,24,N)
    float* out = (float*)d_out;                     // (B,3,N)

    const int B = in_sizes[1] / 72;
    const int N = in_sizes[0] / (3 * B);

    const int groups = (N + 3) / 4;
    dim3 block(256);
    dim3 grid((groups + 255) / 256, B);
    skin_kernel<<<grid, block>>>(normals, pose, weights, out, N);
}